// round 10
// baseline (speedup 1.0000x reference)
#include <cuda_runtime.h>
#include <cuda_bf16.h>
#include <stdint.h>

// Problem dims
#define Bn  8
#define Cc  256
#define ICc 128
#define Nn  4096   // 64*64
#define Mm  1024   // 32*32
#define BN_EPS 1e-5f

// ---------------- scratch (__device__ globals; no allocation) ----------------
__device__ float d_alpha[Cc];
__device__ float d_bias_t[1];
__device__ float d_st[Bn * Nn];
__device__ float d_gT[Bn * Mm * ICc];       // pooled g, (b, m, ic)
__device__ float d_phiT[Bn * Mm * ICc];     // pooled phi, (b, m, ic)
__device__ float d_ss[Bn * Mm];             // s_p sorted descending
__device__ int   d_perm[Bn * Mm];
__device__ float d_cs1[Bn * 8 * ICc];
__device__ float d_cs2[Bn * 8 * ICc];
__device__ float d_G1[Bn * 1025 * ICc];
__device__ float d_G2[Bn * 1025 * ICc];
__device__ float d_wy[Bn * Cc * Nn];
__device__ float d_bnsum[Cc];
__device__ float d_bnsq[Cc];
__device__ float d_scale[Cc];
__device__ float d_shift[Cc];

// pre-split bf16 operands (hi/lo)
__device__ __align__(16) __nv_bfloat16 d_wgh[ICc * Cc];
__device__ __align__(16) __nv_bfloat16 d_wgl[ICc * Cc];
__device__ __align__(16) __nv_bfloat16 d_wph[ICc * Cc];
__device__ __align__(16) __nv_bfloat16 d_wpl[ICc * Cc];
__device__ __align__(16) __nv_bfloat16 d_wWh[Cc * ICc];
__device__ __align__(16) __nv_bfloat16 d_wWl[Cc * ICc];
__device__ __align__(16) __nv_bfloat16 d_xh[Bn * Cc * Nn];
__device__ __align__(16) __nv_bfloat16 d_xl[Bn * Cc * Nn];
__device__ __align__(16) __nv_bfloat16 d_yh[Bn * ICc * Nn];
__device__ __align__(16) __nv_bfloat16 d_yl[Bn * ICc * Nn];

// ================= mma.sync / cp.async helpers (sm_80+ baseline) =============
__device__ __forceinline__ uint32_t smem_u32(const void* p) {
    uint32_t a;
    asm("{ .reg .u64 t; cvta.to.shared.u64 t, %1; cvt.u32.u64 %0, t; }" : "=r"(a) : "l"(p));
    return a;
}
__device__ __forceinline__ void cpa16(uint32_t smem, const void* g) {
    asm volatile("cp.async.cg.shared.global [%0], [%1], 16;" :: "r"(smem), "l"(g));
}
#define CPA_COMMIT() asm volatile("cp.async.commit_group;" ::: "memory")
__device__ __forceinline__ void cpa_wait(int n) {
    if (n <= 0)      asm volatile("cp.async.wait_group 0;" ::: "memory");
    else if (n == 1) asm volatile("cp.async.wait_group 1;" ::: "memory");
    else             asm volatile("cp.async.wait_group 2;" ::: "memory");
}

__device__ __forceinline__ void ldsm4(uint32_t* r, uint32_t addr) {
    asm volatile("ldmatrix.sync.aligned.m8n8.x4.shared.b16 {%0,%1,%2,%3}, [%4];"
                 : "=r"(r[0]), "=r"(r[1]), "=r"(r[2]), "=r"(r[3]) : "r"(addr));
}
__device__ __forceinline__ void ldsm4t(uint32_t* r, uint32_t addr) {
    asm volatile("ldmatrix.sync.aligned.m8n8.x4.trans.shared.b16 {%0,%1,%2,%3}, [%4];"
                 : "=r"(r[0]), "=r"(r[1]), "=r"(r[2]), "=r"(r[3]) : "r"(addr));
}
__device__ __forceinline__ void mma16816(float* d, const uint32_t* a, const uint32_t* b) {
    asm volatile("mma.sync.aligned.m16n8k16.row.col.f32.bf16.bf16.f32 "
                 "{%0,%1,%2,%3},{%4,%5,%6,%7},{%8,%9},{%0,%1,%2,%3};"
                 : "+f"(d[0]), "+f"(d[1]), "+f"(d[2]), "+f"(d[3])
                 : "r"(a[0]), "r"(a[1]), "r"(a[2]), "r"(a[3]), "r"(b[0]), "r"(b[1]));
}

// ---------------- deep-pipelined warp-MMA GEMM mainloop ----------------------
// acc[8][4] = A[128, K] * B[K, Nn-slice]; all operands pre-split bf16 hi/lo in
// gmem. 4-stage cp.async ring, K chunk = 32, stage = 32KB:
//   Ah @0 (128x32 bf16, 64B rows), Al @8K, Bh @16K (32x128, 256B rows), Bl @24K.
// Block: 512 thr = 16 warps (4M x 4N), warp tile 32x32.
#define STAGE_BYTES 32768
#define NSTAGES 4
#define GEMM_SMEM (NSTAGES * STAGE_BYTES)

__device__ __forceinline__ void issue_chunk(const __nv_bfloat16* __restrict__ Ahsrc,
                                            const __nv_bfloat16* __restrict__ Alsrc,
                                            int lda,
                                            const __nv_bfloat16* __restrict__ Bhsrc,
                                            const __nv_bfloat16* __restrict__ Blsrc,
                                            int k0, int n0, uint32_t sb, int t) {
    {   // A: 128 rows x 32 cols, 64B rows; thread -> row r = t>>2, seg s = t&3
        int r = t >> 2, s = t & 3;
        uint32_t off = ((uint32_t)r * 64 + (uint32_t)s * 16) ^ (((uint32_t)(r >> 1) & 3) << 4);
        cpa16(sb + off, Ahsrc + (size_t)r * lda + k0 + s * 8);
        cpa16(sb + 8192 + off, Alsrc + (size_t)r * lda + k0 + s * 8);
    }
    {   // B: 32 rows x 128 cols, 256B rows; thread -> row r = t>>4, seg q = t&15
        int r = t >> 4, q = t & 15;
        uint32_t off = ((uint32_t)r * 256 + (uint32_t)q * 16) ^ (((uint32_t)r & 7) << 4);
        cpa16(sb + 16384 + off, Bhsrc + (size_t)(k0 + r) * Nn + n0 + q * 8);
        cpa16(sb + 24576 + off, Blsrc + (size_t)(k0 + r) * Nn + n0 + q * 8);
    }
}

template <int NCH>
__device__ __forceinline__ void gemm_mainloop(const __nv_bfloat16* __restrict__ Ahsrc,
                                              const __nv_bfloat16* __restrict__ Alsrc,
                                              int lda,
                                              const __nv_bfloat16* __restrict__ Bhsrc,
                                              const __nv_bfloat16* __restrict__ Blsrc,
                                              int n0, char* sm, float (*acc)[4]) {
    const uint32_t smB = smem_u32(sm);
    const int t = threadIdx.x;
    const int warp = t >> 5, lane = t & 31;
    const int wm = (warp >> 2) * 32;   // warp M offset
    const int wn = (warp & 3) * 32;    // warp N offset

#pragma unroll
    for (int i = 0; i < 8; i++)
#pragma unroll
        for (int j = 0; j < 4; j++) acc[i][j] = 0.f;

#pragma unroll
    for (int p = 0; p < 3 && p < NCH; p++) {
        issue_chunk(Ahsrc, Alsrc, lda, Bhsrc, Blsrc, p * 32, n0,
                    smB + (uint32_t)p * STAGE_BYTES, t);
        CPA_COMMIT();
    }

#pragma unroll
    for (int ch = 0; ch < NCH; ch++) {
        cpa_wait(NCH - ch - 1 < 2 ? NCH - ch - 1 : 2);
        __syncthreads();
        if (ch + 3 < NCH) {
            issue_chunk(Ahsrc, Alsrc, lda, Bhsrc, Blsrc, (ch + 3) * 32, n0,
                        smB + (uint32_t)((ch + 3) & (NSTAGES - 1)) * STAGE_BYTES, t);
            CPA_COMMIT();
        }
        const uint32_t sb = smB + (uint32_t)(ch & (NSTAGES - 1)) * STAGE_BYTES;

#pragma unroll
        for (int ks = 0; ks < 2; ks++) {
            uint32_t bh[8], bl[8];
#pragma unroll
            for (int p = 0; p < 2; p++) {
                uint32_t krow = (uint32_t)(ks * 16 + (lane & 15));
                uint32_t off = krow * 256 + (uint32_t)(wn + p * 16) * 2 + ((lane >> 4) << 4);
                off ^= (krow & 7) << 4;
                ldsm4t(bh + p * 4, sb + 16384 + off);
                ldsm4t(bl + p * 4, sb + 24576 + off);
            }
#pragma unroll
            for (int mi = 0; mi < 2; mi++) {
                uint32_t ah[4], al[4];
                uint32_t row = (uint32_t)(wm + mi * 16 + (lane & 15));
                uint32_t off = row * 64 + (uint32_t)(ks * 32) + ((lane >> 4) << 4);
                off ^= ((row >> 1) & 3) << 4;
                ldsm4(ah, sb + off);
                ldsm4(al, sb + 8192 + off);
#pragma unroll
                for (int ni = 0; ni < 4; ni++) {
                    const uint32_t* fh = &bh[(ni >> 1) * 4 + (ni & 1) * 2];
                    const uint32_t* fl = &bl[(ni >> 1) * 4 + (ni & 1) * 2];
                    float* d = acc[mi * 4 + ni];
                    mma16816(d, ah, fh);
                    mma16816(d, ah, fl);
                    mma16816(d, al, fh);
                }
            }
        }
    }
}

// ---------------- weight pre-split -------------------------------------------
__global__ void k_prep(const float* __restrict__ g_w, const float* __restrict__ phi_w,
                       const float* __restrict__ W_w) {
    int i = blockIdx.x * 256 + threadIdx.x;   // < 32768
    float v = g_w[i];
    __nv_bfloat16 h = __float2bfloat16(v);
    d_wgh[i] = h; d_wgl[i] = __float2bfloat16(v - __bfloat162float(h));
    v = phi_w[i]; h = __float2bfloat16(v);
    d_wph[i] = h; d_wpl[i] = __float2bfloat16(v - __bfloat162float(h));
    v = W_w[i]; h = __float2bfloat16(v);
    d_wWh[i] = h; d_wWl[i] = __float2bfloat16(v - __bfloat162float(h));
}

// GEMM1 + fused 2x2 maxpool + transpose.
// Tile n0=nt*128 covers image rows {2nt, 2nt+1}; pooled row ph=nt:
// (gT|phiT)[(b*Mm + nt*32 + pw)*ICc + o] = max2x2 + bias[o].
__global__ __launch_bounds__(512) void k_mma1(const float* __restrict__ g_b,
                                              const float* __restrict__ phi_b) {
    extern __shared__ char sm[];
    int nt = blockIdx.x, which = blockIdx.y, b = blockIdx.z;
    float acc[8][4];
    gemm_mainloop<8>(which ? d_wph : d_wgh, which ? d_wpl : d_wgl, Cc,
                     d_xh + (size_t)b * Cc * Nn, d_xl + (size_t)b * Cc * Nn,
                     nt * 128, sm, acc);

    const int t = threadIdx.x;
    const int warp = t >> 5, lane = t & 31;
    const int wm = (warp >> 2) * 32;
    const int rowsel = (warp & 3) >> 1;        // wn >= 64
    const int pwbase = (warp & 1) * 16;

    __syncthreads();                           // all warps done reading smem
    float* hbuf = reinterpret_cast<float*>(sm);   // [128][66]
#pragma unroll
    for (int mi = 0; mi < 2; mi++) {
        int o0 = wm + mi * 16 + (lane >> 2);
#pragma unroll
        for (int ni = 0; ni < 4; ni++) {
            const float* d = acc[mi * 4 + ni];
            int slot = rowsel * 32 + pwbase + ni * 4 + (lane & 3);
            hbuf[o0 * 66 + slot] = fmaxf(d[0], d[1]);
            hbuf[(o0 + 8) * 66 + slot] = fmaxf(d[2], d[3]);
        }
    }
    __syncthreads();

    const float* bias = which ? phi_b : g_b;
    float* dst = (which ? d_phiT : d_gT) + ((size_t)b * Mm + nt * 32) * ICc;
    int o = (t & 31) * 4;
    float4 bv = *reinterpret_cast<const float4*>(bias + o);
#pragma unroll
    for (int j = 0; j < 2; j++) {
        int pw = (t >> 5) + 16 * j;
        float4 v;
        v.x = fmaxf(hbuf[(o + 0) * 66 + pw], hbuf[(o + 0) * 66 + 32 + pw]) + bv.x;
        v.y = fmaxf(hbuf[(o + 1) * 66 + pw], hbuf[(o + 1) * 66 + 32 + pw]) + bv.y;
        v.z = fmaxf(hbuf[(o + 2) * 66 + pw], hbuf[(o + 2) * 66 + 32 + pw]) + bv.z;
        v.w = fmaxf(hbuf[(o + 3) * 66 + pw], hbuf[(o + 3) * 66 + 32 + pw]) + bv.w;
        *reinterpret_cast<float4*>(dst + (size_t)pw * ICc + o) = v;
    }
}

// GEMM2 + fused BN-stat accumulation.
__global__ __launch_bounds__(512) void k_mma2(const float* __restrict__ W_b) {
    extern __shared__ char sm[];
    int nt = blockIdx.x, by = blockIdx.y, b = blockIdx.z;
    int n0 = nt * 128;
    float acc[8][4];
    gemm_mainloop<4>(d_wWh + (size_t)by * 128 * ICc, d_wWl + (size_t)by * 128 * ICc, ICc,
                     d_yh + (size_t)b * ICc * Nn, d_yl + (size_t)b * ICc * Nn,
                     n0, sm, acc);

    const int t = threadIdx.x;
    const int warp = t >> 5, lane = t & 31;
    const int wm = (warp >> 2) * 32;
    const int wn = (warp & 3) * 32;
    const float* bias = W_b + by * 128;
    float* C = d_wy + (size_t)(b * Cc + by * 128) * Nn;

    __syncthreads();                           // mainloop smem dead; reuse
    float* ssum = reinterpret_cast<float*>(sm);   // [128]
    float* ssq  = ssum + 128;
    if (t < 128) { ssum[t] = 0.f; ssq[t] = 0.f; }
    __syncthreads();

#pragma unroll
    for (int mi = 0; mi < 2; mi++) {
        int o0 = wm + mi * 16 + (lane >> 2);
        float bv0 = bias[o0], bv1 = bias[o0 + 8];
        float s0 = 0.f, q0 = 0.f, s1 = 0.f, q1 = 0.f;
#pragma unroll
        for (int ni = 0; ni < 4; ni++) {
            int col = n0 + wn + ni * 8 + (lane & 3) * 2;
            const float* d = acc[mi * 4 + ni];
            float v0 = d[0] + bv0, v1 = d[1] + bv0;
            float v2 = d[2] + bv1, v3 = d[3] + bv1;
            *reinterpret_cast<float2*>(C + (size_t)o0 * Nn + col) = make_float2(v0, v1);
            *reinterpret_cast<float2*>(C + (size_t)(o0 + 8) * Nn + col) = make_float2(v2, v3);
            s0 += v0 + v1; q0 += v0 * v0 + v1 * v1;
            s1 += v2 + v3; q1 += v2 * v2 + v3 * v3;
        }
#pragma unroll
        for (int off = 1; off < 4; off <<= 1) {
            s0 += __shfl_xor_sync(0xffffffffu, s0, off);
            q0 += __shfl_xor_sync(0xffffffffu, q0, off);
            s1 += __shfl_xor_sync(0xffffffffu, s1, off);
            q1 += __shfl_xor_sync(0xffffffffu, q1, off);
        }
        if ((lane & 3) == 0) {
            atomicAdd(&ssum[o0], s0);
            atomicAdd(&ssq[o0], q0);
            atomicAdd(&ssum[o0 + 8], s1);
            atomicAdd(&ssq[o0 + 8], q1);
        }
    }
    __syncthreads();
    if (t < 128) {
        atomicAdd(&d_bnsum[by * 128 + t], ssum[t]);
        atomicAdd(&d_bnsq[by * 128 + t], ssq[t]);
    }
}

// ---------------- k_alpha: alpha = theta_w^T w_t ; bias_t = w_t . theta_b ----
// also zeroes BN accumulators for this graph replay
__global__ void k_alpha(const float* __restrict__ theta_w,
                        const float* __restrict__ theta_b,
                        const float* __restrict__ cp_w) {
    int c = threadIdx.x;
    d_bnsum[c] = 0.f;
    d_bnsq[c] = 0.f;
    float a = 0.f;
    for (int ic = 0; ic < ICc; ic++) a += cp_w[ic] * theta_w[ic * Cc + c];
    d_alpha[c] = a;
    __shared__ float red[256];
    red[c] = (c < ICc) ? cp_w[c] * theta_b[c] : 0.f;
    __syncthreads();
    for (int s = 128; s > 0; s >>= 1) {
        if (c < s) red[c] += red[c + s];
        __syncthreads();
    }
    if (c == 0) d_bias_t[0] = red[0];
}

// ---------------- k_st: s_t = alpha·x[:,n] + bias_t; also splits x -> bf16 ---
__global__ __launch_bounds__(256) void k_st(const float* __restrict__ x) {
    __shared__ float part[8][33];
    int lane = threadIdx.x & 31, grp = threadIdx.x >> 5;
    int b = blockIdx.y, n = blockIdx.x * 32 + lane;
    const float* xb = x + (size_t)b * Cc * Nn + n;
    __nv_bfloat16* xh = d_xh + (size_t)b * Cc * Nn + n;
    __nv_bfloat16* xl = d_xl + (size_t)b * Cc * Nn + n;
    float s = 0.f;
#pragma unroll
    for (int j = 0; j < 32; j++) {
        int c = grp * 32 + j;
        float v = xb[(size_t)c * Nn];
        s = fmaf(d_alpha[c], v, s);
        __nv_bfloat16 h = __float2bfloat16(v);
        xh[(size_t)c * Nn] = h;
        xl[(size_t)c * Nn] = __float2bfloat16(v - __bfloat162float(h));
    }
    part[grp][lane] = s;
    __syncthreads();
    if (grp == 0) {
        float acc = d_bias_t[0];
#pragma unroll
        for (int g = 0; g < 8; g++) acc += part[g][lane];
        d_st[b * Nn + n] = acc;
    }
}

// ---------------- k_sort: s_p compute + bitonic sort (descending) ------------
__global__ void k_sort(const float* __restrict__ cp_w) {
    __shared__ float key[1024];
    __shared__ int   idx[1024];
    __shared__ float wp[128];
    int tid = threadIdx.x, b = blockIdx.x;
    if (tid < 128) wp[tid] = cp_w[ICc + tid];
    __syncthreads();

    // s_p[m] = wp . phiT[b][m]
    {
        const float4* p = reinterpret_cast<const float4*>(d_phiT + ((size_t)b * Mm + tid) * ICc);
        float s = 0.f;
#pragma unroll 8
        for (int j = 0; j < 32; j++) {
            float4 v = p[j];
            const float* w = wp + j * 4;
            s = fmaf(v.x, w[0], s); s = fmaf(v.y, w[1], s);
            s = fmaf(v.z, w[2], s); s = fmaf(v.w, w[3], s);
        }
        key[tid] = s;
        idx[tid] = tid;
    }
    __syncthreads();

    for (int k = 2; k <= 1024; k <<= 1) {
        for (int j = k >> 1; j > 0; j >>= 1) {
            int ixj = tid ^ j;
            if (ixj > tid) {
                bool up = ((tid & k) == 0);
                float a = key[tid], c = key[ixj];
                bool sw = up ? (a < c) : (a > c);
                if (sw) {
                    key[tid] = c; key[ixj] = a;
                    int t = idx[tid]; idx[tid] = idx[ixj]; idx[ixj] = t;
                }
            }
            __syncthreads();
        }
    }
    d_ss[b * Mm + tid] = key[tid];
    d_perm[b * Mm + tid] = idx[tid];
}

// ---------------- prefix tables over sorted order ----------------------------
__global__ void k_p1() {
    __shared__ int   sperm[128];
    __shared__ float sval[128];
    int b = blockIdx.y, ch = blockIdx.x, ic = threadIdx.x;
    sperm[ic] = d_perm[b * Mm + ch * 128 + ic];
    sval[ic]  = d_ss[b * Mm + ch * 128 + ic];
    __syncthreads();
    float s1 = 0.f, s2 = 0.f;
#pragma unroll 4
    for (int j = 0; j < 128; j++) {
        float g = d_gT[((size_t)b * Mm + sperm[j]) * ICc + ic];
        s1 += g;
        s2 = fmaf(sval[j], g, s2);
    }
    d_cs1[((size_t)b * 8 + ch) * ICc + ic] = s1;
    d_cs2[((size_t)b * 8 + ch) * ICc + ic] = s2;
}

__global__ void k_p2() {
    __shared__ int   sperm[128];
    __shared__ float sval[128];
    int b = blockIdx.y, ch = blockIdx.x, ic = threadIdx.x;
    sperm[ic] = d_perm[b * Mm + ch * 128 + ic];
    sval[ic]  = d_ss[b * Mm + ch * 128 + ic];
    __syncthreads();
    float r1 = 0.f, r2 = 0.f;
    for (int cc = 0; cc < ch; cc++) {
        r1 += d_cs1[((size_t)b * 8 + cc) * ICc + ic];
        r2 += d_cs2[((size_t)b * 8 + cc) * ICc + ic];
    }
#pragma unroll 4
    for (int j = 0; j < 128; j++) {
        int kg = ch * 128 + j;
        d_G1[((size_t)b * 1025 + kg) * ICc + ic] = r1;
        d_G2[((size_t)b * 1025 + kg) * ICc + ic] = r2;
        float g = d_gT[((size_t)b * Mm + sperm[j]) * ICc + ic];
        r1 += g;
        r2 = fmaf(sval[j], g, r2);
    }
    if (ch == 7) {
        d_G1[((size_t)b * 1025 + 1024) * ICc + ic] = r1;
        d_G2[((size_t)b * 1025 + 1024) * ICc + ic] = r2;
    }
}

// ---------------- y: yT[b][ic][n] (split bf16) -------------------------------
__global__ __launch_bounds__(256) void k_y() {
    extern __shared__ float tile[];          // [128][129]
    __shared__ int   s_lo[128];
    __shared__ float s_st[128];
    int t = threadIdx.x;
    int b = blockIdx.y, n0 = blockIdx.x * 128;

    if (t < 128) {
        float st = d_st[b * Nn + n0 + t];
        float tgt = -st;
        const float* ss = d_ss + b * Mm;
        int lo = 0, hi = 1024;
        while (lo < hi) {
            int mid = (lo + hi) >> 1;
            if (ss[mid] > tgt) lo = mid + 1; else hi = mid;
        }
        s_lo[t] = lo;
        s_st[t] = st;
    }
    __syncthreads();

    int ic = t & 127, nh = t >> 7;
    for (int j = 0; j < 64; j++) {
        int nl = nh * 64 + j;
        int lo = s_lo[nl];
        float st = s_st[nl];
        size_t gidx = ((size_t)b * 1025 + lo) * ICc + ic;
        tile[nl * 129 + ic] = (st * d_G1[gidx] + d_G2[gidx]) * (1.0f / 1024.0f);
    }
    __syncthreads();

    int nl = t & 127, half = t >> 7;
    for (int j = 0; j < 64; j++) {
        int ico = half * 64 + j;
        float v = tile[nl * 129 + ico];
        __nv_bfloat16 h = __float2bfloat16(v);
        size_t idx = ((size_t)b * ICc + ico) * Nn + n0 + nl;
        d_yh[idx] = h;
        d_yl[idx] = __float2bfloat16(v - __bfloat162float(h));
    }
}

// ---------------- BN stats -> scale/shift ------------------------------------
__global__ void k_bnstats(const float* __restrict__ gamma, const float* __restrict__ beta) {
    int c = threadIdx.x;
    const float inv_cnt = 1.0f / (Bn * Nn);
    float mean = d_bnsum[c] * inv_cnt;
    float var = d_bnsq[c] * inv_cnt - mean * mean;
    float scale = rsqrtf(var + BN_EPS) * gamma[c];
    d_scale[c] = scale;
    d_shift[c] = beta[c] - mean * scale;
}

// ---------------- final: out = wy*scale + shift + x --------------------------
__global__ void k_final(const float* __restrict__ x, float* __restrict__ out) {
    size_t i = ((size_t)blockIdx.x * 256 + threadIdx.x) * 4;
    int c = (int)((i / Nn) % Cc);
    float4 wv = *reinterpret_cast<const float4*>(d_wy + i);
    float4 xv = *reinterpret_cast<const float4*>(x + i);
    float sc = d_scale[c], sh = d_shift[c];
    float4 o;
    o.x = fmaf(wv.x, sc, sh) + xv.x;
    o.y = fmaf(wv.y, sc, sh) + xv.y;
    o.z = fmaf(wv.z, sc, sh) + xv.z;
    o.w = fmaf(wv.w, sc, sh) + xv.w;
    *reinterpret_cast<float4*>(out + i) = o;
}

// ---------------- launch -----------------------------------------------------
extern "C" void kernel_launch(void* const* d_in, const int* in_sizes, int n_in,
                              void* d_out, int out_size) {
    const float* x       = (const float*)d_in[0];
    const float* g_w     = (const float*)d_in[1];
    const float* g_b     = (const float*)d_in[2];
    const float* theta_w = (const float*)d_in[3];
    const float* theta_b = (const float*)d_in[4];
    const float* phi_w   = (const float*)d_in[5];
    const float* phi_b   = (const float*)d_in[6];
    const float* cp_w    = (const float*)d_in[7];
    const float* W_w     = (const float*)d_in[8];
    const float* W_b     = (const float*)d_in[9];
    const float* bn_g    = (const float*)d_in[10];
    const float* bn_b    = (const float*)d_in[11];
    float* out = (float*)d_out;

    static bool attr_done = false;
    if (!attr_done) {
        cudaFuncSetAttribute(k_mma1, cudaFuncAttributeMaxDynamicSharedMemorySize, GEMM_SMEM);
        cudaFuncSetAttribute(k_mma2, cudaFuncAttributeMaxDynamicSharedMemorySize, GEMM_SMEM);
        cudaFuncSetAttribute(k_y, cudaFuncAttributeMaxDynamicSharedMemorySize, 128 * 129 * 4);
        attr_done = true;
    }

    k_alpha<<<1, 256>>>(theta_w, theta_b, cp_w);
    k_prep<<<128, 256>>>(g_w, phi_w, W_w);
    k_st<<<dim3(Nn / 32, Bn), 256>>>(x);
    k_mma1<<<dim3(32, 2, Bn), 512, GEMM_SMEM>>>(g_b, phi_b);
    k_sort<<<Bn, 1024>>>(cp_w);
    k_p1<<<dim3(8, Bn), 128>>>();
    k_p2<<<dim3(8, Bn), 128>>>();
    k_y<<<dim3(32, Bn), 256, 128 * 129 * 4>>>();
    k_mma2<<<dim3(32, 2, Bn), 512, GEMM_SMEM>>>(W_b);
    k_bnstats<<<1, 256>>>(bn_g, bn_b);
    k_final<<<(Bn * Cc * Nn) / (256 * 4), 256>>>(x, out);
}